// round 15
// baseline (speedup 1.0000x reference)
#include <cuda_runtime.h>
#include <math.h>

#define NB      8
#define NT      250
#define MTOK    2000          // NB*NT tokens
#define DMODEL  512
#define DINNER  1024
#define DSTATE  64
#define FLATK   120000

typedef unsigned long long ull;

// ---------------- scratch (static device globals; no allocation) ------------
__device__ __align__(256) float g_xz[MTOK * 2048];       // in_proj out  (x | z)
__device__ __align__(256) float g_xconv[MTOK * DINNER];  // conv+silu out
__device__ __align__(256) float g_xdbl[MTOK * 160];      // x_proj out (dt|B|C)
__device__ __align__(256) float g_dt[MTOK * DINNER];     // softplus(dt_proj)
__device__ __align__(256) float g_yact[MTOK * DINNER];   // ssm out * silu(z)
__device__ __align__(256) float g_ytmp[MTOK * 512];      // out_proj (pre-selu)
__device__ __align__(256) float g_yperm[NB * FLATK];     // selu + permuted
__device__ __align__(256) float g_fc1[NB * 512];

__device__ __forceinline__ float siluf(float x) { return x / (1.f + __expf(-x)); }

__device__ __forceinline__ ull pk2(float lo, float hi) {
    ull r; asm("mov.b64 %0, {%1, %2};" : "=l"(r) : "f"(lo), "f"(hi)); return r;
}
__device__ __forceinline__ void upk2(ull v, float& lo, float& hi) {
    asm("mov.b64 {%0, %1}, %2;" : "=f"(lo), "=f"(hi) : "l"(v));
}
__device__ __forceinline__ void ffma2(ull& d, ull a, ull b) {
    asm("fma.rn.f32x2 %0, %1, %2, %0;" : "+l"(d) : "l"(a), "l"(b));
}

// ---------------- packed-f32x2 GEMM: C[M,N] = A[M,K] * W[N,K]^T -------------
// BM=128, BN=64, BK=16, 128 threads, 8x8 microtile (f32x2-paired along M).
// EPI: 0 = plain store, 1 = atomicAdd (split-K), 3 = +bias then softplus.
template <int EPI>
__global__ void __launch_bounds__(128, 2) gemm128(
    const float* __restrict__ A, const float* __restrict__ W,
    float* __restrict__ C, const float* __restrict__ bias,
    int M, int N, int K, int lda, int ldb, int ldc, int kChunk)
{
    __shared__ __align__(16) float As[16][128];
    __shared__ __align__(16) float Ws[16][64];
    const int tid = threadIdx.x;
    const int m0  = blockIdx.x * 128;
    const int n0  = blockIdx.y * 64;
    const int kBeg = blockIdx.z * kChunk;
    const int kEnd = min(K, kBeg + kChunk);

    const int tm = tid & 15;           // 0..15  (m group)
    const int tn = tid >> 4;           // 0..7   (n group)

    // loader roles
    const int am  = m0 + tid;          // A row this thread loads
    const bool aok = am < M;
    const int bn  = n0 + (tid & 63);   // W row this thread loads
    const int bq  = tid >> 6;          // 0/1 -> k sub-offset 8*bq
    const bool bok = bn < N;

    ull acc[4][8];
#pragma unroll
    for (int p = 0; p < 4; p++)
#pragma unroll
        for (int j = 0; j < 8; j++) acc[p][j] = 0ull;

    float4 ar[4], br[2];
    // prefetch first K-slab
#pragma unroll
    for (int q = 0; q < 4; q++)
        ar[q] = aok ? *(const float4*)(A + (size_t)am * lda + kBeg + q * 4)
                    : make_float4(0.f, 0.f, 0.f, 0.f);
#pragma unroll
    for (int q = 0; q < 2; q++)
        br[q] = bok ? *(const float4*)(W + (size_t)bn * ldb + kBeg + bq * 8 + q * 4)
                    : make_float4(0.f, 0.f, 0.f, 0.f);

    for (int kc = kBeg; kc < kEnd; kc += 16) {
        // stage prefetched slab to smem (transposed: [k][m] / [k][n])
#pragma unroll
        for (int q = 0; q < 4; q++) {
            As[q * 4 + 0][tid] = ar[q].x; As[q * 4 + 1][tid] = ar[q].y;
            As[q * 4 + 2][tid] = ar[q].z; As[q * 4 + 3][tid] = ar[q].w;
        }
#pragma unroll
        for (int q = 0; q < 2; q++) {
            Ws[bq * 8 + q * 4 + 0][tid & 63] = br[q].x;
            Ws[bq * 8 + q * 4 + 1][tid & 63] = br[q].y;
            Ws[bq * 8 + q * 4 + 2][tid & 63] = br[q].z;
            Ws[bq * 8 + q * 4 + 3][tid & 63] = br[q].w;
        }
        __syncthreads();

        const int kn = kc + 16;
        if (kn < kEnd) {
#pragma unroll
            for (int q = 0; q < 4; q++)
                ar[q] = aok ? *(const float4*)(A + (size_t)am * lda + kn + q * 4)
                            : make_float4(0.f, 0.f, 0.f, 0.f);
#pragma unroll
            for (int q = 0; q < 2; q++)
                br[q] = bok ? *(const float4*)(W + (size_t)bn * ldb + kn + bq * 8 + q * 4)
                            : make_float4(0.f, 0.f, 0.f, 0.f);
        }

#pragma unroll
        for (int kk = 0; kk < 16; kk++) {
            // A m-pairs come straight from smem as 64-bit pairs
            ulonglong2 aLo = *(const ulonglong2*)&As[kk][tm * 4];
            ulonglong2 aHi = *(const ulonglong2*)&As[kk][64 + tm * 4];
            float4 bL = *(const float4*)&Ws[kk][tn * 4];
            float4 bH = *(const float4*)&Ws[kk][32 + tn * 4];
            ull ap[4] = { aLo.x, aLo.y, aHi.x, aHi.y };
            ull bd[8] = { pk2(bL.x, bL.x), pk2(bL.y, bL.y),
                          pk2(bL.z, bL.z), pk2(bL.w, bL.w),
                          pk2(bH.x, bH.x), pk2(bH.y, bH.y),
                          pk2(bH.z, bH.z), pk2(bH.w, bH.w) };
#pragma unroll
            for (int p = 0; p < 4; p++)
#pragma unroll
                for (int j = 0; j < 8; j++)
                    ffma2(acc[p][j], ap[p], bd[j]);
        }
        __syncthreads();
    }

    // ---------------- epilogue ----------------
#pragma unroll
    for (int p = 0; p < 4; p++) {
        const int mr = m0 + ((p < 2) ? (tm * 4 + 2 * p) : (64 + tm * 4 + 2 * (p - 2)));
        if (mr >= M) continue;
        const bool r2 = (mr + 1) < M;
#pragma unroll
        for (int j = 0; j < 8; j++) {
            const int nn = n0 + ((j < 4) ? (tn * 4 + j) : (32 + tn * 4 + (j - 4)));
            if (nn >= N) continue;
            float v0, v1; upk2(acc[p][j], v0, v1);
            if (EPI == 0) {
                C[(size_t)mr * ldc + nn] = v0;
                if (r2) C[(size_t)(mr + 1) * ldc + nn] = v1;
            } else if (EPI == 1) {
                atomicAdd(C + (size_t)mr * ldc + nn, v0);
                if (r2) atomicAdd(C + (size_t)(mr + 1) * ldc + nn, v1);
            } else { // EPI == 3: bias + softplus
                float x0 = v0 + bias[nn];
                C[(size_t)mr * ldc + nn] = (x0 > 20.f) ? x0 : log1pf(expf(x0));
                if (r2) {
                    float x1 = v1 + bias[nn];
                    C[(size_t)(mr + 1) * ldc + nn] = (x1 > 20.f) ? x1 : log1pf(expf(x1));
                }
            }
        }
    }
}

// ---------------- depthwise causal conv (width 4) + SiLU --------------------
__global__ void __launch_bounds__(256) conv_silu_kernel(
    const float* __restrict__ xz, const float* __restrict__ cw,
    const float* __restrict__ cb, float* __restrict__ out)
{
    const int idx = blockIdx.x * 256 + threadIdx.x;   // MTOK*DINNER
    const int d = idx & (DINNER - 1);
    const int m = idx >> 10;
    const int t = m % NT;
    const int mb = m - t;                              // b*NT
    float acc = cb[d];
#pragma unroll
    for (int k = 0; k < 4; k++) {
        const int tt = t - 3 + k;
        if (tt >= 0)
            acc = fmaf(xz[(size_t)(mb + tt) * 2048 + d], cw[d * 4 + k], acc);
    }
    out[idx] = siluf(acc);
}

__global__ void zero_kernel(float* __restrict__ p, int n)
{
    int i = blockIdx.x * 256 + threadIdx.x;
    if (i < n) p[i] = 0.f;
}

// ---------------- selective scan: warp per (b,d), 2 states/lane -------------
__global__ void __launch_bounds__(256) scan_kernel(
    const float* __restrict__ dtb, const float* __restrict__ xdbl,
    const float* __restrict__ xconv, const float* __restrict__ xz,
    const float* __restrict__ A_log, const float* __restrict__ Dp,
    float* __restrict__ yact)
{
    const int warp = threadIdx.x >> 5;
    const int lane = threadIdx.x & 31;
    const int b = blockIdx.x >> 7;                    // /128
    const int d = ((blockIdx.x & 127) << 3) + warp;   // 0..1023

    const float a0 = -__expf(A_log[d * DSTATE + 2 * lane]);
    const float a1 = -__expf(A_log[d * DSTATE + 2 * lane + 1]);
    const float Dv = Dp[d];
    float h0 = 0.f, h1 = 0.f;
    const int mBase = b * NT;

    for (int t = 0; t < NT; t++) {
        const int m = mBase + t;
        const float dtv = __ldg(&dtb[(size_t)m * DINNER + d]);
        const float uv  = __ldg(&xconv[(size_t)m * DINNER + d]);
        const float zv  = __ldg(&xz[(size_t)m * 2048 + DINNER + d]);
        const float2 Bv = *(const float2*)&xdbl[(size_t)m * 160 + 32 + 2 * lane];
        const float2 Cv = *(const float2*)&xdbl[(size_t)m * 160 + 96 + 2 * lane];
        const float dtu = dtv * uv;
        h0 = fmaf(h0, __expf(dtv * a0), dtu * Bv.x);
        h1 = fmaf(h1, __expf(dtv * a1), dtu * Bv.y);
        float p = fmaf(h0, Cv.x, h1 * Cv.y);
#pragma unroll
        for (int off = 16; off; off >>= 1)
            p += __shfl_xor_sync(0xffffffffu, p, off);
        if (lane == 0) {
            const float y = fmaf(uv, Dv, p);
            yact[(size_t)m * DINNER + d] = y * siluf(zv);
        }
    }
}

// ---------------- selu + permute (out_proj tail), coalesced writes ----------
__global__ void __launch_bounds__(256) selu_permute_kernel(
    const float* __restrict__ ytmp, float* __restrict__ yperm)
{
    const int o = blockIdx.x * 256 + threadIdx.x;
    if (o >= NB * FLATK) return;
    const int b = o / FLATK, r = o - b * FLATK;
    const int f = r / 5000,  q = r - f * 5000;
    const int t = q / 20,    g = q - t * 20;
    const int n = f + 24 * g;
    const float v = ytmp[(size_t)(b * NT + t) * 512 + n];
    const float SC = 1.0507009873554805f;      // selu scale
    const float SA = 1.7580993408473766f;      // scale*alpha
    yperm[o] = (v > 0.f) ? SC * v : SA * (expf(v) - 1.f);
}

// ---------------- fc1: [8,120000] x [512,120000]^T, 4 n per block -----------
__global__ void __launch_bounds__(256) fc1_kernel(
    const float* __restrict__ yperm, const float* __restrict__ w1,
    const float* __restrict__ b1, float* __restrict__ out1)
{
    __shared__ __align__(16) float acts[8][1024];
    __shared__ float red2[8][32];
    const int tid = threadIdx.x;
    const int n0  = blockIdx.x * 4;
    const int lane = tid & 31, warp = tid >> 5;

    float acc[8][4];
#pragma unroll
    for (int bi = 0; bi < 8; bi++)
#pragma unroll
        for (int j = 0; j < 4; j++) acc[bi][j] = 0.f;

    for (int k0 = 0; k0 < FLATK; k0 += 1024) {
        const int len = min(1024, FLATK - k0);
        for (int i = tid; i < 8 * 1024; i += 256) {
            const int bb = i >> 10, kk = i & 1023;
            acts[bb][kk] = (kk < len) ? yperm[(size_t)bb * FLATK + k0 + kk] : 0.f;
        }
        __syncthreads();
        const int kk = tid * 4;
        if (kk < len) {
            float4 av[8];
#pragma unroll
            for (int bi = 0; bi < 8; bi++)
                av[bi] = *(const float4*)&acts[bi][kk];
#pragma unroll
            for (int j = 0; j < 4; j++) {
                const float4 wv = *(const float4*)(w1 + (size_t)(n0 + j) * FLATK + k0 + kk);
#pragma unroll
                for (int bi = 0; bi < 8; bi++) {
                    acc[bi][j] = fmaf(av[bi].x, wv.x, acc[bi][j]);
                    acc[bi][j] = fmaf(av[bi].y, wv.y, acc[bi][j]);
                    acc[bi][j] = fmaf(av[bi].z, wv.z, acc[bi][j]);
                    acc[bi][j] = fmaf(av[bi].w, wv.w, acc[bi][j]);
                }
            }
        }
        __syncthreads();
    }

#pragma unroll
    for (int idx = 0; idx < 32; idx++) {
        float v = acc[idx >> 2][idx & 3];
#pragma unroll
        for (int off = 16; off; off >>= 1)
            v += __shfl_xor_sync(0xffffffffu, v, off);
        if (lane == 0) red2[warp][idx] = v;
    }
    __syncthreads();
    if (tid < 32) {
        float s = 0.f;
#pragma unroll
        for (int w = 0; w < 8; w++) s += red2[w][tid];
        const int bi = tid >> 2, j = tid & 3;
        out1[bi * 512 + n0 + j] = s + b1[n0 + j];
    }
}

// ---------------- fc2 -> fc3 -> fc4 (all linear, no activations) ------------
__global__ void __launch_bounds__(256) head_kernel(
    const float* __restrict__ out1,
    const float* __restrict__ w2, const float* __restrict__ b2,
    const float* __restrict__ w3, const float* __restrict__ b3,
    const float* __restrict__ w4, const float* __restrict__ b4,
    float* __restrict__ out)
{
    __shared__ __align__(16) float s1[512];
    __shared__ __align__(16) float s2[256];
    __shared__ __align__(16) float s3[64];
    const int b = blockIdx.x;
    const int tid = threadIdx.x;

    for (int i = tid; i < 512; i += 256) s1[i] = out1[b * 512 + i];
    __syncthreads();
    {
        float a = b2[tid];
        const float4* wr = (const float4*)(w2 + (size_t)tid * 512);
#pragma unroll 4
        for (int k = 0; k < 128; k++) {
            const float4 wv = wr[k];
            const float4 sv = *(const float4*)&s1[k * 4];
            a = fmaf(sv.x, wv.x, a); a = fmaf(sv.y, wv.y, a);
            a = fmaf(sv.z, wv.z, a); a = fmaf(sv.w, wv.w, a);
        }
        s2[tid] = a;
    }
    __syncthreads();
    if (tid < 64) {
        float a = b3[tid];
        const float4* wr = (const float4*)(w3 + (size_t)tid * 256);
#pragma unroll 4
        for (int k = 0; k < 64; k++) {
            const float4 wv = wr[k];
            const float4 sv = *(const float4*)&s2[k * 4];
            a = fmaf(sv.x, wv.x, a); a = fmaf(sv.y, wv.y, a);
            a = fmaf(sv.z, wv.z, a); a = fmaf(sv.w, wv.w, a);
        }
        s3[tid] = a;
    }
    __syncthreads();
    if (tid < 8) {
        float a = b4[tid];
#pragma unroll
        for (int k = 0; k < 64; k++)
            a = fmaf(s3[k], w4[tid * 64 + k], a);
        out[b * 8 + tid] = a;
    }
}

// ---------------------------------------------------------------------------
extern "C" void kernel_launch(void* const* d_in, const int* in_sizes, int n_in,
                              void* d_out, int out_size)
{
    const float* x          = (const float*)d_in[0];   // [8,5000,24]
    const float* in_proj_w  = (const float*)d_in[1];   // [2048,512]
    const float* conv_w     = (const float*)d_in[2];   // [1024,4]
    const float* conv_b     = (const float*)d_in[3];   // [1024]
    const float* x_proj_w   = (const float*)d_in[4];   // [160,1024]
    const float* dt_proj_w  = (const float*)d_in[5];   // [1024,32]
    const float* dt_proj_b  = (const float*)d_in[6];   // [1024]
    const float* A_log      = (const float*)d_in[7];   // [1024,64]
    const float* Dp         = (const float*)d_in[8];   // [1024]
    const float* out_proj_w = (const float*)d_in[9];   // [512,1024]
    const float* fc1_w      = (const float*)d_in[10];  // [512,120000]
    const float* fc1_b      = (const float*)d_in[11];
    const float* fc2_w      = (const float*)d_in[12];  // [256,512]
    const float* fc2_b      = (const float*)d_in[13];
    const float* fc3_w      = (const float*)d_in[14];  // [64,256]
    const float* fc3_b      = (const float*)d_in[15];
    const float* fc4_w      = (const float*)d_in[16];  // [8,64]
    const float* fc4_b      = (const float*)d_in[17];
    float* out = (float*)d_out;

    float *xz, *xconv, *xdbl, *dtb, *yact, *ytmp, *yperm, *fc1o;
    cudaGetSymbolAddress((void**)&xz,    g_xz);
    cudaGetSymbolAddress((void**)&xconv, g_xconv);
    cudaGetSymbolAddress((void**)&xdbl,  g_xdbl);
    cudaGetSymbolAddress((void**)&dtb,   g_dt);
    cudaGetSymbolAddress((void**)&yact,  g_yact);
    cudaGetSymbolAddress((void**)&ytmp,  g_ytmp);
    cudaGetSymbolAddress((void**)&yperm, g_yperm);
    cudaGetSymbolAddress((void**)&fc1o,  g_fc1);

    // 1) in_proj: xz[2000,2048] = u[2000,480(=K)] * W^T   (pad folded: K=480)
    gemm128<0><<<dim3(16, 32, 1), 128>>>(x, in_proj_w, xz, nullptr,
        MTOK, 2048, 480, 480, DMODEL, 2048, 480);

    // 2) depthwise conv + silu -> xconv[2000,1024]
    conv_silu_kernel<<<(MTOK * DINNER) / 256, 256>>>(xz, conv_w, conv_b, xconv);

    // 3) x_proj (split-K=8, atomicAdd) -> xdbl[2000,160]
    zero_kernel<<<(MTOK * 160 + 255) / 256, 256>>>(xdbl, MTOK * 160);
    gemm128<1><<<dim3(16, 3, 8), 128>>>(xconv, x_proj_w, xdbl, nullptr,
        MTOK, 160, DINNER, DINNER, DINNER, 160, 128);

    // 4) dt_proj + bias + softplus -> dt[2000,1024]
    gemm128<3><<<dim3(16, 16, 1), 128>>>(xdbl, dt_proj_w, dtb, dt_proj_b,
        MTOK, DINNER, 32, 160, 32, DINNER, 32);

    // 5) selective scan + gate -> yact[2000,1024]
    scan_kernel<<<NB * 128, 256>>>(dtb, xdbl, xconv, xz, A_log, Dp, yact);

    // 6) out_proj (split-K=2, atomicAdd) -> ytmp[2000,512]
    zero_kernel<<<(MTOK * 512 + 255) / 256, 256>>>(ytmp, MTOK * 512);
    gemm128<1><<<dim3(16, 8, 2), 128>>>(yact, out_proj_w, ytmp, nullptr,
        MTOK, 512, DINNER, DINNER, DINNER, 512, 512);

    // 6b) selu + permute -> yperm[8,120000]
    selu_permute_kernel<<<(NB * FLATK + 255) / 256, 256>>>(ytmp, yperm);

    // 7) fc1 -> [8,512]
    fc1_kernel<<<128, 256>>>(yperm, fc1_w, fc1_b, fc1o);

    // 8) fc2/fc3/fc4 -> [8,8]
    head_kernel<<<NB, 256>>>(fc1o, fc2_w, fc2_b, fc3_w, fc3_b, fc4_w, fc4_b, out);

    (void)in_sizes; (void)n_in; (void)out_size;
}